// round 5
// baseline (speedup 1.0000x reference)
#include <cuda_runtime.h>
#include <math.h>
#include <float.h>

#define BATCH   256
#define NLEV    4
#define CDIM    8000
#define NTOTAL  10500
#define THREADS 256

// Flat f4 layout for levels 2,1,0: L2 [0,500), L1 [500,600), L0 [600,625)
// Phase A handles level 3 (2000 f4) split in halves of 1000.
// Phase B handles flat [0,313) for h=0, [313,625) for h=1.

struct HalfRes {
    float              s[4];
    unsigned long long key[4];
    float              pad[4];   // pad to 96B to keep halves apart-ish
};

__device__ HalfRes      g_half[BATCH][2];
__device__ float        g_tlog[BATCH][4];
__device__ float        g_part[BATCH];
__device__ unsigned int g_rowcnt[BATCH];   // zero-init; reset each replay
__device__ unsigned int g_count = 0;

__device__ __forceinline__ unsigned long long amax_key(float v, int idx) {
    unsigned u = __float_as_uint(v);
    u = (u & 0x80000000u) ? ~u : (u | 0x80000000u);   // order-preserving map
    return ((unsigned long long)u << 32) | (unsigned)(0x7fffffff - idx);
}

__device__ __forceinline__ void acc1(float v, int eidx, float& s, float& av, int& ai) {
    s += __expf(v);
    if (v > av) { av = v; ai = eidx; }   // strict >: first (smallest idx) wins
}

__device__ __forceinline__ void wred(float& s, float& av, int& ai) {
    #pragma unroll
    for (int o = 16; o > 0; o >>= 1) {
        float s2  = __shfl_down_sync(0xffffffffu, s,  o);
        float av2 = __shfl_down_sync(0xffffffffu, av, o);
        int   ai2 = __shfl_down_sync(0xffffffffu, ai, o);
        s += s2;
        if (av2 > av || (av2 == av && ai2 < ai)) { av = av2; ai = ai2; }
    }
}

__global__ void __launch_bounds__(THREADS, 4) taxa_kernel(
    const float* __restrict__ y_pred,
    const int*   __restrict__ y_true,
    const float* __restrict__ H,
    float*       __restrict__ out)
{
    const int bh   = blockIdx.x;
    const int b    = bh >> 1;
    const int h    = bh & 1;
    const int tid  = threadIdx.x;
    const int warp = tid >> 5;
    const int lane = tid & 31;

    const float* base = y_pred + (size_t)b * NLEV * CDIM;

    // Early prefetch of target logits (h==0 block, tid 0) — overlaps the sweep.
    if (h == 0 && tid == 0) {
        int4 t4 = *reinterpret_cast<const int4*>(y_true + b * 4);
        int t1 = min(max(t4.y, 0), 399);
        int t2 = min(max(t4.z, 0), 1999);
        int t3 = min(max(t4.w, 0), 7999);
        g_tlog[b][1] = __ldg(base + 1 * CDIM + t1);
        g_tlog[b][2] = __ldg(base + 2 * CDIM + t2);
        g_tlog[b][3] = __ldg(base + 3 * CDIM + t3);
    }

    // ---- Issue ALL loads up-front (6 LDG.128 per thread, unpredicated) ----
    const float4* r3 = reinterpret_cast<const float4*>(base + 3 * CDIM);
    const int aBase = h * 1000, aEnd = aBase + 1000;

    float4 va[4]; int aIdx[4]; bool aP[4];
    #pragma unroll
    for (int k = 0; k < 4; k++) {
        int idx = aBase + tid + k * 256;
        aP[k]   = idx < aEnd;
        aIdx[k] = aP[k] ? idx : (aEnd - 1);
        va[k]   = __ldg(r3 + aIdx[k]);
    }

    const int bStart = h ? 313 : 0;
    const int bEnd   = h ? 625 : 313;
    float4 vb[2]; int bJ[2], bE4[2]; bool bP[2];
    #pragma unroll
    for (int k = 0; k < 2; k++) {
        int f  = bStart + tid + k * 256;
        bP[k]  = f < bEnd;
        int fc = bP[k] ? f : bStart;
        int j, e4;
        if (fc < 500)      { j = 2; e4 = fc; }
        else if (fc < 600) { j = 1; e4 = fc - 500; }
        else               { j = 0; e4 = fc - 600; }
        bJ[k] = j; bE4[k] = e4;
        vb[k] = __ldg(reinterpret_cast<const float4*>(base + j * CDIM) + e4);
    }

    // ---- Accumulate ----
    float s3 = 0.f, s2 = 0.f, s1 = 0.f, s0 = 0.f;
    float av3 = -FLT_MAX, av2 = -FLT_MAX, av1 = -FLT_MAX, av0 = -FLT_MAX;
    int   ai3 = 0x7fffffff, ai2 = 0x7fffffff, ai1 = 0x7fffffff, ai0 = 0x7fffffff;

    #pragma unroll
    for (int k = 0; k < 4; k++) {
        float4 v = va[k];
        if (!aP[k]) { v.x = v.y = v.z = v.w = -FLT_MAX; }   // exp -> 0, never argmax
        int e = 4 * aIdx[k];
        acc1(v.x, e + 0, s3, av3, ai3);
        acc1(v.y, e + 1, s3, av3, ai3);
        acc1(v.z, e + 2, s3, av3, ai3);
        acc1(v.w, e + 3, s3, av3, ai3);
    }
    #pragma unroll
    for (int k = 0; k < 2; k++) {
        float4 v = vb[k];
        if (!bP[k]) { v.x = v.y = v.z = v.w = -FLT_MAX; }
        int e = 4 * bE4[k];
        int j = bJ[k];
        if (j == 2) {
            acc1(v.x, e + 0, s2, av2, ai2); acc1(v.y, e + 1, s2, av2, ai2);
            acc1(v.z, e + 2, s2, av2, ai2); acc1(v.w, e + 3, s2, av2, ai2);
        } else if (j == 1) {
            acc1(v.x, e + 0, s1, av1, ai1); acc1(v.y, e + 1, s1, av1, ai1);
            acc1(v.z, e + 2, s1, av1, ai1); acc1(v.w, e + 3, s1, av1, ai1);
        } else {
            acc1(v.x, e + 0, s0, av0, ai0); acc1(v.y, e + 1, s0, av0, ai0);
            acc1(v.z, e + 2, s0, av0, ai0); acc1(v.w, e + 3, s0, av0, ai0);
        }
    }

    // ---- Warp reduce all 4 level triplets ----
    wred(s3, av3, ai3);
    wred(s2, av2, ai2);
    wred(s1, av1, ai1);
    wred(s0, av0, ai0);

    __shared__ float s_s[4][8], s_av[4][8];
    __shared__ int   s_ai[4][8];
    __shared__ float s_fs[4], s_fav[4];
    __shared__ int   s_fai[4];
    __shared__ int   s_role;

    if (lane == 0) {
        s_s[3][warp] = s3; s_av[3][warp] = av3; s_ai[3][warp] = ai3;
        s_s[2][warp] = s2; s_av[2][warp] = av2; s_ai[2][warp] = ai2;
        s_s[1][warp] = s1; s_av[1][warp] = av1; s_ai[1][warp] = ai1;
        s_s[0][warp] = s0; s_av[0][warp] = av0; s_ai[0][warp] = ai0;
    }
    __syncthreads();

    // Warp 0: lane = lev*8 + w, segmented reduce within 8-lane groups.
    if (warp == 0) {
        int lev = lane >> 3, w = lane & 7;
        float rs = s_s[lev][w], rav = s_av[lev][w];
        int   rai = s_ai[lev][w];
        #pragma unroll
        for (int o = 4; o > 0; o >>= 1) {
            float s2_  = __shfl_down_sync(0xffffffffu, rs,  o);
            float av2_ = __shfl_down_sync(0xffffffffu, rav, o);
            int   ai2_ = __shfl_down_sync(0xffffffffu, rai, o);
            if (w + o < 8) {
                rs += s2_;
                if (av2_ > rav || (av2_ == rav && ai2_ < rai)) { rav = av2_; rai = ai2_; }
            }
        }
        if (w == 0) { s_fs[lev] = rs; s_fav[lev] = rav; s_fai[lev] = rai; }
    }
    __syncthreads();

    // ---- tid0 tail: publish half, maybe combine row, maybe finish grid ----
    if (tid == 0) {
        HalfRes* me = &g_half[b][h];
        #pragma unroll
        for (int lv = 0; lv < 4; lv++) {
            me->s[lv]   = s_fs[lv];
            me->key[lv] = amax_key(s_fav[lv], s_fai[lv]);
        }
        __threadfence();
        unsigned r = atomicAdd(&g_rowcnt[b], 1u);
        int fin = 0;
        if (r == 1) {   // second half to arrive: combine this row
            __threadfence();
            float cs[4]; unsigned long long ck[4];
            #pragma unroll
            for (int lv = 0; lv < 4; lv++) {
                // fixed slot order -> deterministic sum
                float sa = __ldcg(&g_half[b][0].s[lv]);
                float sb = __ldcg(&g_half[b][1].s[lv]);
                cs[lv] = sa + sb;
                unsigned long long ka =
                    __ldcg((const unsigned long long*)&g_half[b][0].key[lv]);
                unsigned long long kb =
                    __ldcg((const unsigned long long*)&g_half[b][1].key[lv]);
                ck[lv] = (ka > kb) ? ka : kb;
            }
            int a0 = 0x7fffffff - (int)(unsigned)(ck[0] & 0xffffffffu);
            int a1 = 0x7fffffff - (int)(unsigned)(ck[1] & 0xffffffffu);
            int a2 = 0x7fffffff - (int)(unsigned)(ck[2] & 0xffffffffu);
            int a3 = 0x7fffffff - (int)(unsigned)(ck[3] & 0xffffffffu);
            int g0 = a0, g1 = a1 + 100, g2 = a2 + 500, g3 = a3 + 2500;

            float nll1 = logf(cs[1]) - __ldcg(&g_tlog[b][1]);
            float nll2 = logf(cs[2]) - __ldcg(&g_tlog[b][2]);
            float nll3 = logf(cs[3]) - __ldcg(&g_tlog[b][3]);

            float h01 = __ldg(&H[(size_t)g0 * NTOTAL + g1]);
            float h12 = __ldg(&H[(size_t)g1 * NTOTAL + g2]);
            float h23 = __ldg(&H[(size_t)g2 * NTOTAL + g3]);
            float c01 = (h01 == 1.0f) ? 1.0f : 0.0f;
            float c12 = (h12 == 1.0f) ? 1.0f : 0.0f;
            float c23 = (h23 == 1.0f) ? 1.0f : 0.0f;

            const float E    = 2.7182817459106445f;   // float32(np.e)
            const float invB = 1.0f / (float)BATCH;
            float p = 0.25f * (E * c01 + nll1 * invB)
                    + 0.15f * (E * c12 + nll2 * invB)
                    + 0.10f * (E * c23 + nll3 * invB);

            g_part[b] = p;
            __threadfence();
            unsigned q = atomicAdd(&g_count, 1u);
            fin = (q == BATCH - 1);
        }
        s_role = fin;
    }
    __syncthreads();

    // ---- Last row-finisher block: deterministic 256-way final sum + reset ----
    if (s_role) {
        float v = __ldcg(&g_part[tid]);
        __shared__ float red[THREADS];
        red[tid] = v;
        __syncthreads();
        #pragma unroll
        for (int o = 128; o > 0; o >>= 1) {
            if (tid < o) red[tid] += red[tid + o];
            __syncthreads();
        }
        g_rowcnt[tid] = 0;                 // reset per-row counters for replay
        if (tid == 0) { out[0] = red[0]; g_count = 0; }
    }
}

extern "C" void kernel_launch(void* const* d_in, const int* in_sizes, int n_in,
                              void* d_out, int out_size) {
    const float* y_pred = (const float*)d_in[0];
    const int*   y_true = (const int*)d_in[1];
    const float* H      = (const float*)d_in[2];
    float*       out    = (float*)d_out;

    taxa_kernel<<<BATCH * 2, THREADS>>>(y_pred, y_true, H, out);
}

// round 6
// speedup vs baseline: 1.2234x; 1.2234x over previous
#include <cuda_runtime.h>
#include <math.h>
#include <float.h>

#define BATCH   256
#define NLEV    4
#define CDIM    8000
#define NTOTAL  10500
#define THREADS 512

// Scratch (allocation-free): per-row partial + completion counter.
__device__ float        g_part[BATCH];
__device__ unsigned int g_count = 0;

__device__ __forceinline__ void amax_comb(float& av, int& ai, float av2, int ai2) {
    if (av2 > av || (av2 == av && ai2 < ai)) { av = av2; ai = ai2; }
}

// Exp-sum + argmax over one level's prefix (N4 float4s); ITERS loads issued up-front.
template<int N4, int STRIDE, int ITERS, bool NEED_SUM>
__device__ __forceinline__ void accum(const float4* __restrict__ row4, int lt,
                                      float& s, float& av, int& ai) {
    float4 v[ITERS]; int id[ITERS]; bool p[ITERS];
    #pragma unroll
    for (int k = 0; k < ITERS; k++) {
        int idx = lt + k * STRIDE;
        p[k]  = idx < N4;
        id[k] = p[k] ? idx : (N4 - 1);
        v[k]  = __ldg(&row4[id[k]]);
    }
    float s0 = 0.f, s1 = 0.f, s2 = 0.f, s3 = 0.f;
    float a0 = -FLT_MAX, a1 = -FLT_MAX, a2 = -FLT_MAX, a3 = -FLT_MAX;
    int   i0 = 0x7fffffff, i1 = 0x7fffffff, i2 = 0x7fffffff, i3 = 0x7fffffff;
    #pragma unroll
    for (int k = 0; k < ITERS; k++) {
        float4 w = v[k];
        if (!p[k]) { w.x = w.y = w.z = w.w = -FLT_MAX; }
        int e = 4 * id[k];
        if (NEED_SUM) {
            s0 += __expf(w.x); s1 += __expf(w.y);
            s2 += __expf(w.z); s3 += __expf(w.w);
        }
        if (w.x > a0) { a0 = w.x; i0 = e + 0; }
        if (w.y > a1) { a1 = w.y; i1 = e + 1; }
        if (w.z > a2) { a2 = w.z; i2 = e + 2; }
        if (w.w > a3) { a3 = w.w; i3 = e + 3; }
    }
    s = (s0 + s1) + (s2 + s3);
    av = a0; ai = i0;
    amax_comb(av, ai, a1, i1);
    amax_comb(av, ai, a2, i2);
    amax_comb(av, ai, a3, i3);
}

__global__ void __launch_bounds__(THREADS, 2) fused_taxanet_kernel(
    const float* __restrict__ y_pred,
    const int*   __restrict__ y_true,
    const float* __restrict__ H,
    float*       __restrict__ out)
{
    const int b    = blockIdx.x;
    const int tid  = threadIdx.x;
    const int warp = tid >> 5;
    const int lane = tid & 31;

    __shared__ float    s_s[16], s_av[16];
    __shared__ int      s_ai[16];
    __shared__ float    s_tlogit[4];
    __shared__ int      s_g[4];
    __shared__ float    s_nll[4];
    __shared__ int      s_fin;

    const float* base = y_pred + (size_t)b * NLEV * CDIM;

    if (warp == 15) {
        // Prefetch target logits (overlaps the sweep).
        if (lane < 3) {
            const int jj  = lane + 1;
            const int szs = (jj == 1) ? 400 : (jj == 2) ? 2000 : 8000;
            int tgt = __ldg(&y_true[b * NLEV + jj]);
            tgt = min(max(tgt, 0), szs - 1);
            s_tlogit[jj] = __ldg(base + (size_t)jj * CDIM + tgt);
        }
        if (lane == 0) { s_s[15] = 0.f; s_av[15] = -FLT_MAX; s_ai[15] = 0x7fffffff; }
    } else {
        // Segments: warps [0,8)->L3, [8,12)->L2, [12,14)->L1, [14]->L0
        int j, seg_base;
        if (warp < 8)       { j = 3; seg_base = 0;  }
        else if (warp < 12) { j = 2; seg_base = 8;  }
        else if (warp < 14) { j = 1; seg_base = 12; }
        else                { j = 0; seg_base = 14; }
        const int lt = tid - seg_base * 32;

        const float4* row4 = reinterpret_cast<const float4*>(base + (size_t)j * CDIM);

        float s, av; int ai;
        if (j == 3)      accum<2000, 256, 8, true >(row4, lt, s, av, ai);
        else if (j == 2) accum< 500, 128, 4, true >(row4, lt, s, av, ai);
        else if (j == 1) accum< 100,  64, 2, true >(row4, lt, s, av, ai);
        else             accum<  25,  32, 1, false>(row4, lt, s, av, ai);

        #pragma unroll
        for (int o = 16; o > 0; o >>= 1) {
            float s2  = __shfl_down_sync(0xffffffffu, s,  o);
            float av2 = __shfl_down_sync(0xffffffffu, av, o);
            int   ai2 = __shfl_down_sync(0xffffffffu, ai, o);
            s += s2;
            amax_comb(av, ai, av2, ai2);
        }
        if (lane == 0) { s_s[warp] = s; s_av[warp] = av; s_ai[warp] = ai; }
    }
    __syncthreads();

    // Warp 0: segmented reduce of 16 warp partials.
    if (warp == 0) {
        float rs = 0.f, rav = -FLT_MAX; int rai = 0x7fffffff;
        if (lane < 16) { rs = s_s[lane]; rav = s_av[lane]; rai = s_ai[lane]; }
        const int segsz   = (lane < 8) ? 8 : (lane < 12) ? 4 : (lane < 14) ? 2 : 1;
        const int segbase = (lane < 8) ? 0 : (lane < 12) ? 8 : (lane < 14) ? 12 : 14;
        const int w = lane - segbase;
        #pragma unroll
        for (int o = 4; o > 0; o >>= 1) {
            float s2  = __shfl_down_sync(0xffffffffu, rs,  o);
            float av2 = __shfl_down_sync(0xffffffffu, rav, o);
            int   ai2 = __shfl_down_sync(0xffffffffu, rai, o);
            if (w + o < segsz) {
                rs += s2;
                amax_comb(rav, rai, av2, ai2);
            }
        }
        if (lane == 0)       { s_g[3] = rai; s_nll[3] = __logf(rs) - s_tlogit[3]; }
        else if (lane == 8)  { s_g[2] = rai; s_nll[2] = __logf(rs) - s_tlogit[2]; }
        else if (lane == 12) { s_g[1] = rai; s_nll[1] = __logf(rs) - s_tlogit[1]; }
        else if (lane == 14) { s_g[0] = rai; }
    }
    __syncthreads();

    if (tid == 0) {
        const int g0 = s_g[0];
        const int g1 = s_g[1] + 100;
        const int g2 = s_g[2] + 500;
        const int g3 = s_g[3] + 2500;

        float h01 = __ldg(&H[(size_t)g0 * NTOTAL + g1]);
        float h12 = __ldg(&H[(size_t)g1 * NTOTAL + g2]);
        float h23 = __ldg(&H[(size_t)g2 * NTOTAL + g3]);
        float c01 = (h01 == 1.0f) ? 1.0f : 0.0f;
        float c12 = (h12 == 1.0f) ? 1.0f : 0.0f;
        float c23 = (h23 == 1.0f) ? 1.0f : 0.0f;

        const float E    = 2.7182817459106445f;   // float32(np.e)
        const float invB = 1.0f / (float)BATCH;
        float p = 0.25f * (E * c01 + s_nll[1] * invB)
                + 0.15f * (E * c12 + s_nll[2] * invB)
                + 0.10f * (E * c23 + s_nll[3] * invB);

        g_part[b] = p;
        __threadfence();
        unsigned q = atomicAdd(&g_count, 1u);
        s_fin = (q == BATCH - 1);
    }
    __syncthreads();

    // Last block: deterministic shuffle-based 256-way sum (1 barrier).
    if (s_fin) {
        float v = (tid < BATCH) ? __ldcg(&g_part[tid]) : 0.f;
        #pragma unroll
        for (int o = 16; o > 0; o >>= 1)
            v += __shfl_down_sync(0xffffffffu, v, o);
        __shared__ float red[16];
        if (lane == 0) red[warp] = v;
        __syncthreads();
        if (warp == 0) {
            float r = (lane < 16) ? red[lane] : 0.f;
            #pragma unroll
            for (int o = 8; o > 0; o >>= 1)
                r += __shfl_down_sync(0xffffffffu, r, o);
            if (lane == 0) { out[0] = r; g_count = 0; }
        }
    }
}

extern "C" void kernel_launch(void* const* d_in, const int* in_sizes, int n_in,
                              void* d_out, int out_size) {
    const float* y_pred = (const float*)d_in[0];
    const int*   y_true = (const int*)d_in[1];
    const float* H      = (const float*)d_in[2];
    float*       out    = (float*)d_out;

    fused_taxanet_kernel<<<BATCH, THREADS>>>(y_pred, y_true, H, out);
}

// round 7
// speedup vs baseline: 1.2321x; 1.0071x over previous
#include <cuda_runtime.h>
#include <math.h>
#include <float.h>

#define BATCH   256
#define NLEV    4
#define CDIM    8000
#define NTOTAL  10500
#define THREADS 512

// Single packed accumulator: bits [0,48) fixed-point sum (x 2^32, all p >= 0),
// bits [48,...) block-arrival count. Integer adds are exactly commutative ->
// deterministic result independent of arrival order. Zero-init; the finishing
// block resets it for graph replay.
__device__ unsigned long long g_acc = 0ULL;

__device__ __forceinline__ void amax_comb(float& av, int& ai, float av2, int ai2) {
    if (av2 > av || (av2 == av && ai2 < ai)) { av = av2; ai = ai2; }
}

// Exp-sum + argmax over one level's prefix (N4 float4s); ITERS loads issued up-front.
template<int N4, int STRIDE, int ITERS, bool NEED_SUM>
__device__ __forceinline__ void accum(const float4* __restrict__ row4, int lt,
                                      float& s, float& av, int& ai) {
    float4 v[ITERS]; int id[ITERS]; bool p[ITERS];
    #pragma unroll
    for (int k = 0; k < ITERS; k++) {
        int idx = lt + k * STRIDE;
        p[k]  = idx < N4;
        id[k] = p[k] ? idx : (N4 - 1);
        v[k]  = __ldg(&row4[id[k]]);
    }
    float s0 = 0.f, s1 = 0.f, s2 = 0.f, s3 = 0.f;
    float a0 = -FLT_MAX, a1 = -FLT_MAX, a2 = -FLT_MAX, a3 = -FLT_MAX;
    int   i0 = 0x7fffffff, i1 = 0x7fffffff, i2 = 0x7fffffff, i3 = 0x7fffffff;
    #pragma unroll
    for (int k = 0; k < ITERS; k++) {
        float4 w = v[k];
        if (!p[k]) { w.x = w.y = w.z = w.w = -FLT_MAX; }
        int e = 4 * id[k];
        if (NEED_SUM) {
            s0 += __expf(w.x); s1 += __expf(w.y);
            s2 += __expf(w.z); s3 += __expf(w.w);
        }
        if (w.x > a0) { a0 = w.x; i0 = e + 0; }
        if (w.y > a1) { a1 = w.y; i1 = e + 1; }
        if (w.z > a2) { a2 = w.z; i2 = e + 2; }
        if (w.w > a3) { a3 = w.w; i3 = e + 3; }
    }
    s = (s0 + s1) + (s2 + s3);
    av = a0; ai = i0;
    amax_comb(av, ai, a1, i1);
    amax_comb(av, ai, a2, i2);
    amax_comb(av, ai, a3, i3);
}

__global__ void __launch_bounds__(THREADS, 2) fused_taxanet_kernel(
    const float* __restrict__ y_pred,
    const int*   __restrict__ y_true,
    const float* __restrict__ H,
    float*       __restrict__ out)
{
    const int b    = blockIdx.x;
    const int tid  = threadIdx.x;
    const int warp = tid >> 5;
    const int lane = tid & 31;

    __shared__ float s_s[16], s_av[16];
    __shared__ int   s_ai[16];
    __shared__ float s_tlogit[4];

    const float* base = y_pred + (size_t)b * NLEV * CDIM;

    if (warp == 15) {
        // Prefetch target logits (overlaps the sweep).
        if (lane < 3) {
            const int jj  = lane + 1;
            const int szs = (jj == 1) ? 400 : (jj == 2) ? 2000 : 8000;
            int tgt = __ldg(&y_true[b * NLEV + jj]);
            tgt = min(max(tgt, 0), szs - 1);
            s_tlogit[jj] = __ldg(base + (size_t)jj * CDIM + tgt);
        }
        if (lane == 0) { s_s[15] = 0.f; s_av[15] = -FLT_MAX; s_ai[15] = 0x7fffffff; }
    } else {
        // Segments: warps [0,8)->L3, [8,12)->L2, [12,14)->L1, [14]->L0
        int j, seg_base;
        if (warp < 8)       { j = 3; seg_base = 0;  }
        else if (warp < 12) { j = 2; seg_base = 8;  }
        else if (warp < 14) { j = 1; seg_base = 12; }
        else                { j = 0; seg_base = 14; }
        const int lt = tid - seg_base * 32;

        const float4* row4 = reinterpret_cast<const float4*>(base + (size_t)j * CDIM);

        float s, av; int ai;
        if (j == 3)      accum<2000, 256, 8, true >(row4, lt, s, av, ai);
        else if (j == 2) accum< 500, 128, 4, true >(row4, lt, s, av, ai);
        else if (j == 1) accum< 100,  64, 2, true >(row4, lt, s, av, ai);
        else             accum<  25,  32, 1, false>(row4, lt, s, av, ai);

        #pragma unroll
        for (int o = 16; o > 0; o >>= 1) {
            float s2  = __shfl_down_sync(0xffffffffu, s,  o);
            float av2 = __shfl_down_sync(0xffffffffu, av, o);
            int   ai2 = __shfl_down_sync(0xffffffffu, ai, o);
            s += s2;
            amax_comb(av, ai, av2, ai2);
        }
        if (lane == 0) { s_s[warp] = s; s_av[warp] = av; s_ai[warp] = ai; }
    }
    __syncthreads();   // the ONLY block-wide barrier

    // Warp 0 finishes the whole block: segmented reduce, H gathers, one atomic.
    if (warp == 0) {
        float rs = 0.f, rav = -FLT_MAX; int rai = 0x7fffffff;
        if (lane < 16) { rs = s_s[lane]; rav = s_av[lane]; rai = s_ai[lane]; }
        const int segsz   = (lane < 8) ? 8 : (lane < 12) ? 4 : (lane < 14) ? 2 : 1;
        const int segbase = (lane < 8) ? 0 : (lane < 12) ? 8 : (lane < 14) ? 12 : 14;
        const int w = lane - segbase;
        #pragma unroll
        for (int o = 4; o > 0; o >>= 1) {
            float s2  = __shfl_down_sync(0xffffffffu, rs,  o);
            float av2 = __shfl_down_sync(0xffffffffu, rav, o);
            int   ai2 = __shfl_down_sync(0xffffffffu, rai, o);
            if (w + o < segsz) {
                rs += s2;
                amax_comb(rav, rai, av2, ai2);
            }
        }
        // Heads: lane0->L3, lane8->L2, lane12->L1, lane14->L0.
        float nllv = 0.f;
        if (lane == 0)       nllv = __logf(rs) - s_tlogit[3];
        else if (lane == 8)  nllv = __logf(rs) - s_tlogit[2];
        else if (lane == 12) nllv = __logf(rs) - s_tlogit[1];

        // Gather head results into lane 0.
        const unsigned FULL = 0xffffffffu;
        int   g3i = __shfl_sync(FULL, rai, 0);
        int   g2i = __shfl_sync(FULL, rai, 8);
        int   g1i = __shfl_sync(FULL, rai, 12);
        int   g0i = __shfl_sync(FULL, rai, 14);
        float nll3 = __shfl_sync(FULL, nllv, 0);
        float nll2 = __shfl_sync(FULL, nllv, 8);
        float nll1 = __shfl_sync(FULL, nllv, 12);

        if (lane == 0) {
            const int g0 = g0i;
            const int g1 = g1i + 100;
            const int g2 = g2i + 500;
            const int g3 = g3i + 2500;

            float h01 = __ldg(&H[(size_t)g0 * NTOTAL + g1]);
            float h12 = __ldg(&H[(size_t)g1 * NTOTAL + g2]);
            float h23 = __ldg(&H[(size_t)g2 * NTOTAL + g3]);
            float c01 = (h01 == 1.0f) ? 1.0f : 0.0f;
            float c12 = (h12 == 1.0f) ? 1.0f : 0.0f;
            float c23 = (h23 == 1.0f) ? 1.0f : 0.0f;

            const float E    = 2.7182817459106445f;   // float32(np.e)
            const float invB = 1.0f / (float)BATCH;
            float p = 0.25f * (E * c01 + nll1 * invB)
                    + 0.15f * (E * c12 + nll2 * invB)
                    + 0.10f * (E * c23 + nll3 * invB);
            p = fmaxf(p, 0.0f);   // mathematically guaranteed; guards fixed-point

            // Fixed-point pack: sum in [0,48), arrival count at bit 48.
            unsigned long long fx =
                (unsigned long long)__float2ll_rn(p * 4294967296.0f);   // * 2^32
            unsigned long long old =
                atomicAdd(&g_acc, fx + (1ULL << 48));
            if ((old >> 48) == BATCH - 1) {
                unsigned long long tot = (old & 0xFFFFFFFFFFFFULL) + fx;
                out[0] = (float)((double)tot * (1.0 / 4294967296.0));
                g_acc = 0ULL;   // reset for graph replay
            }
        }
    }
}

extern "C" void kernel_launch(void* const* d_in, const int* in_sizes, int n_in,
                              void* d_out, int out_size) {
    const float* y_pred = (const float*)d_in[0];
    const int*   y_true = (const int*)d_in[1];
    const float* H      = (const float*)d_in[2];
    float*       out    = (float*)d_out;

    fused_taxanet_kernel<<<BATCH, THREADS>>>(y_pred, y_true, H, out);
}

// round 8
// speedup vs baseline: 1.2684x; 1.0294x over previous
#include <cuda_runtime.h>
#include <math.h>
#include <float.h>

#define BATCH   256
#define NLEV    4
#define CDIM    8000
#define NTOTAL  10500
#define THREADS 512

// Single packed accumulator: bits [0,48) fixed-point sum (x 2^32, all p >= 0),
// bits [48,...) block-arrival count. Integer adds are exactly commutative ->
// deterministic result independent of arrival order.
__device__ unsigned long long g_acc = 0ULL;

__device__ __forceinline__ void amax_comb(float& av, int& ai, float av2, int ai2) {
    if (av2 > av || (av2 == av && ai2 < ai)) { av = av2; ai = ai2; }
}

// Polynomial exp on the FMA/ALU pipes (no MUFU). Rel err <= ~5e-5.
// Valid for x >= -80 handled via clamp (exp(-80) ~ 2^-115, still normal).
__device__ __forceinline__ float fexp_poly(float x) {
    float t = fmaxf(x, -80.0f) * 1.4426950408889634f;   // x * log2(e)
    float r = t + 12582912.0f;                           // round-to-nearest magic
    int   k = __float_as_int(r) - 0x4B400000;            // integer part n
    float f = t - (r - 12582912.0f);                     // frac in [-0.5, 0.5]
    float p = 0.009618129107f;                           // 2^f Taylor (ln2^i/i!)
    p = fmaf(p, f, 0.055504108664f);
    p = fmaf(p, f, 0.240226506959f);
    p = fmaf(p, f, 0.693147180560f);
    p = fmaf(p, f, 1.0f);
    return __int_as_float(__float_as_int(p) + (k << 23));
}

// Exp-sum + argmax over one level's prefix (N4 float4s); ITERS loads issued
// up-front. Even batches use MUFU __expf, odd batches use the FMA-pipe poly,
// so the two halves dual-issue on different pipes.
template<int N4, int STRIDE, int ITERS, bool NEED_SUM>
__device__ __forceinline__ void accum(const float4* __restrict__ row4, int lt,
                                      float& s, float& av, int& ai) {
    float4 v[ITERS]; int id[ITERS]; bool p[ITERS];
    #pragma unroll
    for (int k = 0; k < ITERS; k++) {
        int idx = lt + k * STRIDE;
        p[k]  = idx < N4;
        id[k] = p[k] ? idx : (N4 - 1);
        v[k]  = __ldg(&row4[id[k]]);
    }
    float s0 = 0.f, s1 = 0.f, s2 = 0.f, s3 = 0.f;
    float a0 = -FLT_MAX, a1 = -FLT_MAX, a2 = -FLT_MAX, a3 = -FLT_MAX;
    int   i0 = 0x7fffffff, i1 = 0x7fffffff, i2 = 0x7fffffff, i3 = 0x7fffffff;
    #pragma unroll
    for (int k = 0; k < ITERS; k++) {
        float4 w = v[k];
        if (!p[k]) { w.x = w.y = w.z = w.w = -FLT_MAX; }
        int e = 4 * id[k];
        if (NEED_SUM) {
            if ((k & 1) == 0) {
                s0 += __expf(w.x); s1 += __expf(w.y);
                s2 += __expf(w.z); s3 += __expf(w.w);
            } else {
                s0 += fexp_poly(w.x); s1 += fexp_poly(w.y);
                s2 += fexp_poly(w.z); s3 += fexp_poly(w.w);
            }
        }
        if (w.x > a0) { a0 = w.x; i0 = e + 0; }
        if (w.y > a1) { a1 = w.y; i1 = e + 1; }
        if (w.z > a2) { a2 = w.z; i2 = e + 2; }
        if (w.w > a3) { a3 = w.w; i3 = e + 3; }
    }
    s = (s0 + s1) + (s2 + s3);
    av = a0; ai = i0;
    amax_comb(av, ai, a1, i1);
    amax_comb(av, ai, a2, i2);
    amax_comb(av, ai, a3, i3);
}

__global__ void __launch_bounds__(THREADS, 2) fused_taxanet_kernel(
    const float* __restrict__ y_pred,
    const int*   __restrict__ y_true,
    const float* __restrict__ H,
    float*       __restrict__ out)
{
    const int b    = blockIdx.x;
    const int tid  = threadIdx.x;
    const int warp = tid >> 5;
    const int lane = tid & 31;

    __shared__ float s_s[16], s_av[16];
    __shared__ int   s_ai[16];
    __shared__ float s_tlogit[4];

    const float* base = y_pred + (size_t)b * NLEV * CDIM;

    if (warp == 15) {
        // Prefetch target logits (overlaps the sweep).
        if (lane < 3) {
            const int jj  = lane + 1;
            const int szs = (jj == 1) ? 400 : (jj == 2) ? 2000 : 8000;
            int tgt = __ldg(&y_true[b * NLEV + jj]);
            tgt = min(max(tgt, 0), szs - 1);
            s_tlogit[jj] = __ldg(base + (size_t)jj * CDIM + tgt);
        }
        if (lane == 0) { s_s[15] = 0.f; s_av[15] = -FLT_MAX; s_ai[15] = 0x7fffffff; }
    } else {
        // Segments: warps [0,8)->L3, [8,12)->L2, [12,14)->L1, [14]->L0
        int j, seg_base;
        if (warp < 8)       { j = 3; seg_base = 0;  }
        else if (warp < 12) { j = 2; seg_base = 8;  }
        else if (warp < 14) { j = 1; seg_base = 12; }
        else                { j = 0; seg_base = 14; }
        const int lt = tid - seg_base * 32;

        const float4* row4 = reinterpret_cast<const float4*>(base + (size_t)j * CDIM);

        float s, av; int ai;
        if (j == 3)      accum<2000, 256, 8, true >(row4, lt, s, av, ai);
        else if (j == 2) accum< 500, 128, 4, true >(row4, lt, s, av, ai);
        else if (j == 1) accum< 100,  64, 2, true >(row4, lt, s, av, ai);
        else             accum<  25,  32, 1, false>(row4, lt, s, av, ai);

        #pragma unroll
        for (int o = 16; o > 0; o >>= 1) {
            float s2  = __shfl_down_sync(0xffffffffu, s,  o);
            float av2 = __shfl_down_sync(0xffffffffu, av, o);
            int   ai2 = __shfl_down_sync(0xffffffffu, ai, o);
            s += s2;
            amax_comb(av, ai, av2, ai2);
        }
        if (lane == 0) { s_s[warp] = s; s_av[warp] = av; s_ai[warp] = ai; }
    }
    __syncthreads();   // the ONLY block-wide barrier

    // Warp 0 finishes the whole block: segmented reduce, H gathers, one atomic.
    if (warp == 0) {
        float rs = 0.f, rav = -FLT_MAX; int rai = 0x7fffffff;
        if (lane < 16) { rs = s_s[lane]; rav = s_av[lane]; rai = s_ai[lane]; }
        const int segsz   = (lane < 8) ? 8 : (lane < 12) ? 4 : (lane < 14) ? 2 : 1;
        const int segbase = (lane < 8) ? 0 : (lane < 12) ? 8 : (lane < 14) ? 12 : 14;
        const int w = lane - segbase;
        #pragma unroll
        for (int o = 4; o > 0; o >>= 1) {
            float s2  = __shfl_down_sync(0xffffffffu, rs,  o);
            float av2 = __shfl_down_sync(0xffffffffu, rav, o);
            int   ai2 = __shfl_down_sync(0xffffffffu, rai, o);
            if (w + o < segsz) {
                rs += s2;
                amax_comb(rav, rai, av2, ai2);
            }
        }
        // Heads: lane0->L3, lane8->L2, lane12->L1, lane14->L0.
        float nllv = 0.f;
        if (lane == 0)       nllv = __logf(rs) - s_tlogit[3];
        else if (lane == 8)  nllv = __logf(rs) - s_tlogit[2];
        else if (lane == 12) nllv = __logf(rs) - s_tlogit[1];

        const unsigned FULL = 0xffffffffu;
        int   g3i = __shfl_sync(FULL, rai, 0);
        int   g2i = __shfl_sync(FULL, rai, 8);
        int   g1i = __shfl_sync(FULL, rai, 12);
        int   g0i = __shfl_sync(FULL, rai, 14);
        float nll3 = __shfl_sync(FULL, nllv, 0);
        float nll2 = __shfl_sync(FULL, nllv, 8);
        float nll1 = __shfl_sync(FULL, nllv, 12);

        if (lane == 0) {
            const int g0 = g0i;
            const int g1 = g1i + 100;
            const int g2 = g2i + 500;
            const int g3 = g3i + 2500;

            float h01 = __ldg(&H[(size_t)g0 * NTOTAL + g1]);
            float h12 = __ldg(&H[(size_t)g1 * NTOTAL + g2]);
            float h23 = __ldg(&H[(size_t)g2 * NTOTAL + g3]);
            float c01 = (h01 == 1.0f) ? 1.0f : 0.0f;
            float c12 = (h12 == 1.0f) ? 1.0f : 0.0f;
            float c23 = (h23 == 1.0f) ? 1.0f : 0.0f;

            const float E    = 2.7182817459106445f;   // float32(np.e)
            const float invB = 1.0f / (float)BATCH;
            float p = 0.25f * (E * c01 + nll1 * invB)
                    + 0.15f * (E * c12 + nll2 * invB)
                    + 0.10f * (E * c23 + nll3 * invB);
            p = fmaxf(p, 0.0f);   // mathematically guaranteed; guards fixed-point

            unsigned long long fx =
                (unsigned long long)__float2ll_rn(p * 4294967296.0f);   // * 2^32
            unsigned long long old =
                atomicAdd(&g_acc, fx + (1ULL << 48));
            if ((old >> 48) == BATCH - 1) {
                unsigned long long tot = (old & 0xFFFFFFFFFFFFULL) + fx;
                out[0] = (float)((double)tot * (1.0 / 4294967296.0));
                g_acc = 0ULL;   // reset for graph replay
            }
        }
    }
}

extern "C" void kernel_launch(void* const* d_in, const int* in_sizes, int n_in,
                              void* d_out, int out_size) {
    const float* y_pred = (const float*)d_in[0];
    const int*   y_true = (const int*)d_in[1];
    const float* H      = (const float*)d_in[2];
    float*       out    = (float*)d_out;

    fused_taxanet_kernel<<<BATCH, THREADS>>>(y_pred, y_true, H, out);
}